// round 7
// baseline (speedup 1.0000x reference)
#include <cuda_runtime.h>

// Shapes fixed by the reference
#define NB   4
#define DB   8
#define CB   3
#define RB   4
#define KK   5
#define HH   128
#define WW   128
#define HWSZ (HH * WW)
#define TW   32                     // tile width
#define TH   4                      // tile height
#define SH_  (TH + 4)               // 8
#define SW_  (TW + 4)               // 36
#define TILE_FLOATS (CB * SH_ * SW_)        // 864

// Dynamic smem padding: burst tile (3456 B) + pad so total ≈ 30.5 KB/CTA.
// 8 CTAs x 30.5 KB = 244 KB > 228 KB cap -> exactly 7 CTAs/SM resident.
// 4096 blocks / (7*148) = 3.954 waves -> 98.8% scheduling efficiency.
#define DSMEM_BYTES 31232

// Block: x=32 (pixel col), y=2 (si), z=4 (rows). 256 threads.
// Thread: 1 pixel x 1 si-group (r = 2si, 2si+1) x 3 channels = 6 accumulators.
__global__ __launch_bounds__(256, 7)
void adaptive_conv_ps_v7(const float* __restrict__ burst,
                         const float* __restrict__ kernels,
                         float* __restrict__ out)
{
    extern __shared__ float s_[];            // [CB][SH_][SW_] at offset 0, rest = pad
    float (*s)[SH_][SW_] = reinterpret_cast<float (*)[SH_][SW_]>(s_);

    const int nd = blockIdx.z;               // 0..31
    const int h0 = blockIdx.y * TH;
    const int w0 = blockIdx.x * TW;
    const int tx = threadIdx.x;              // 0..31
    const int si = threadIdx.y;              // 0..1
    const int tz = threadIdx.z;              // 0..3
    const int tid = (tz * 2 + si) * 32 + tx;

    // ---- stage burst tile (3 ch, halo 2, zero-pad OOB): 864 elems ----
    const float* bptr = burst + (size_t)nd * CB * HWSZ;
    #pragma unroll
    for (int k = 0; k < 4; k++) {
        int idx = tid + k * 256;
        if (idx < TILE_FLOATS) {
            int c   = idx / (SH_ * SW_);
            int rem = idx - c * (SH_ * SW_);
            int sh  = rem / SW_;
            int sw  = rem - sh * SW_;
            int gh  = h0 + sh - 2;
            int gw  = w0 + sw - 2;
            float v = 0.0f;
            if (gh >= 0 && gh < HH && gw >= 0 && gw < WW)
                v = bptr[c * HWSZ + gh * WW + gw];
            s[c][sh][sw] = v;
        }
    }
    __syncthreads();

    const int h = h0 + tz;
    const int w = w0 + tx;

    float a00 = 0.f, a01 = 0.f;   // acc[c][sj]
    float a10 = 0.f, a11 = 0.f;
    float a20 = 0.f, a21 = 0.f;

    // kernels: (nd, r, i, j, h, w). This thread reads r = 2*si (k0) and 2*si+1 (k1).
    const float* kp = kernels
                    + ((size_t)nd * (RB * KK * KK) + (size_t)si * (2 * KK * KK)) * HWSZ
                    + (size_t)h * WW + w;

    #pragma unroll
    for (int i = 0; i < KK; i++) {
        #pragma unroll
        for (int j = 0; j < KK; j++) {
            const int t = i * KK + j;
            const float k0 = __ldcs(kp + (size_t)t * HWSZ);
            const float k1 = __ldcs(kp + (size_t)(t + KK * KK) * HWSZ);
            const float b0 = s[0][tz + i][tx + j];
            const float b1 = s[1][tz + i][tx + j];
            const float b2 = s[2][tz + i][tx + j];
            a00 = fmaf(k0, b0, a00);  a01 = fmaf(k1, b0, a01);
            a10 = fmaf(k0, b1, a10);  a11 = fmaf(k1, b1, a11);
            a20 = fmaf(k0, b2, a20);  a21 = fmaf(k1, b2, a21);
        }
    }

    // ---- fused pixel shuffle: out (nd, c, 2H, 2W); row 2h+si, cols 2w..2w+1 ----
    float2* o2 = reinterpret_cast<float2*>(out);
    const size_t rowbase = ((size_t)nd * CB) * (2 * HH) + (2 * h + si);
    __stcs(&o2[(rowbase + 0 * 2 * HH) * WW + w], make_float2(a00, a01));
    __stcs(&o2[(rowbase + 1 * 2 * HH) * WW + w], make_float2(a10, a11));
    __stcs(&o2[(rowbase + 2 * 2 * HH) * WW + w], make_float2(a20, a21));
}

extern "C" void kernel_launch(void* const* d_in, const int* in_sizes, int n_in,
                              void* d_out, int out_size)
{
    const float* burst   = (const float*)d_in[0];   // (4,8,3,128,128)
    const float* kernels = (const float*)d_in[1];   // (4,8,4,5,5,128,128)
    float* out = (float*)d_out;                     // (4,8,3,256,256)

    dim3 block(32, 2, 4);                           // 256 threads
    dim3 grid(WW / TW, HH / TH, NB * DB);           // (4, 32, 32) = 4096 blocks
    adaptive_conv_ps_v7<<<grid, block, DSMEM_BYTES>>>(burst, kernels, out);
}

// round 8
// speedup vs baseline: 1.1843x; 1.1843x over previous
#include <cuda_runtime.h>
#include <cstdint>

// Shapes fixed by the reference
#define NB   4
#define DB   8
#define CB   3
#define RB   4
#define KK   5
#define HH   128
#define WW   128
#define HWSZ (HH * WW)
#define TW   32
#define TH   4
#define SH_  (TH + 4)                 // 8
#define SW_  (TW + 4)                 // 36
#define TILE_FLOATS (CB * SH_ * SW_)  // 864

// i-row chunk: 20 planes (q = r*5+j) x 4 rows x 32 w
#define STAGE_FLOATS (20 * TH * TW)   // 2560
#define NUNITS       (STAGE_FLOATS / 4) // 640 x 16B cp.async units

__device__ __forceinline__ void cp16(uint32_t dst, const float* src) {
    asm volatile("cp.async.cg.shared.global [%0], [%1], 16;"
                 :: "r"(dst), "l"(src) : "memory");
}
__device__ __forceinline__ void cp_commit() {
    asm volatile("cp.async.commit_group;" ::: "memory");
}
template <int N>
__device__ __forceinline__ void cp_wait() {
    asm volatile("cp.async.wait_group %0;" :: "n"(N) : "memory");
}

// Block (32,2,4): tx = pixel col, si = r-group, tz = row. 256 threads, 8 CTAs/SM.
__global__ __launch_bounds__(256, 8)
void adaptive_conv_ps_v8(const float* __restrict__ burst,
                         const float* __restrict__ kernels,
                         float* __restrict__ out)
{
    __shared__ alignas(16) float smem[2 * STAGE_FLOATS + TILE_FLOATS];
    float* sb = smem + 2 * STAGE_FLOATS;          // burst tile [CB][SH_][SW_]
    const uint32_t smem_u32 = (uint32_t)__cvta_generic_to_shared(smem);

    const int nd = blockIdx.z;
    const int h0 = blockIdx.y * TH;
    const int w0 = blockIdx.x * TW;
    const int tx = threadIdx.x;                   // 0..31
    const int si = threadIdx.y;                   // 0..1
    const int tz = threadIdx.z;                   // 0..3
    const int tid = (tz * 2 + si) * 32 + tx;

    const float* kbase = kernels + (size_t)nd * (RB * KK * KK) * HWSZ;

    // ---- per-thread cp.async unit constants (unit u -> plane q, row, 16B seg) ----
    // u = q*32 + row*8 + seg ; plane q = r*5+j ; global plane g = r*25 + i*5 + j
    int goff[3];                                  // element offset, i-term excluded
    #pragma unroll
    for (int k = 0; k < 3; k++) {
        int u = tid + k * 256;
        int q   = u >> 5;
        int row = (u >> 3) & 3;
        int seg = u & 7;
        int r = q / 5, j = q - 5 * r;
        goff[k] = (r * 25 + j) * HWSZ + (h0 + row) * WW + w0 + seg * 4;
    }
    const bool has3 = (tid < NUNITS - 512);       // tid < 128

    // ---- kick off chunks 0 and 1 ----
    #pragma unroll
    for (int c = 0; c < 2; c++) {
        const uint32_t stg = smem_u32 + c * (STAGE_FLOATS * 4);
        cp16(stg + tid * 16,         kbase + goff[0] + c * (5 * HWSZ));
        cp16(stg + (tid + 256) * 16, kbase + goff[1] + c * (5 * HWSZ));
        if (has3)
            cp16(stg + (tid + 512) * 16, kbase + goff[2] + c * (5 * HWSZ));
        cp_commit();
    }

    // ---- stage burst tile (3 ch, halo 2, zero-pad OOB) ----
    const float* bptr = burst + (size_t)nd * CB * HWSZ;
    #pragma unroll
    for (int k = 0; k < 4; k++) {
        int idx = tid + k * 256;
        if (idx < TILE_FLOATS) {
            int c   = idx / (SH_ * SW_);
            int rem = idx - c * (SH_ * SW_);
            int sh  = rem / SW_;
            int sw  = rem - sh * SW_;
            int gh  = h0 + sh - 2;
            int gw  = w0 + sw - 2;
            float v = 0.0f;
            if (gh >= 0 && gh < HH && gw >= 0 && gw < WW)
                v = bptr[c * HWSZ + gh * WW + gw];
            sb[idx] = v;
        }
    }
    __syncthreads();

    float a00 = 0.f, a01 = 0.f;
    float a10 = 0.f, a11 = 0.f;
    float a20 = 0.f, a21 = 0.f;

    #pragma unroll
    for (int i = 0; i < KK; i++) {
        if (i < 4) cp_wait<1>(); else cp_wait<0>();
        __syncthreads();                          // everyone's chunk-i bytes visible

        const float* st = smem + (i & 1) * STAGE_FLOATS;
        #pragma unroll
        for (int j = 0; j < KK; j++) {
            const float k0 = st[(10 * si + j)     * (TH * TW) + tz * TW + tx];
            const float k1 = st[(10 * si + 5 + j) * (TH * TW) + tz * TW + tx];
            const float b0 = sb[(0 * SH_ + tz + i) * SW_ + tx + j];
            const float b1 = sb[(1 * SH_ + tz + i) * SW_ + tx + j];
            const float b2 = sb[(2 * SH_ + tz + i) * SW_ + tx + j];
            a00 = fmaf(k0, b0, a00);  a01 = fmaf(k1, b0, a01);
            a10 = fmaf(k0, b1, a10);  a11 = fmaf(k1, b1, a11);
            a20 = fmaf(k0, b2, a20);  a21 = fmaf(k1, b2, a21);
        }
        __syncthreads();                          // stage free for refill

        if (i + 2 < KK) {                         // refill stage (i&1) with chunk i+2
            const uint32_t stg = smem_u32 + (i & 1) * (STAGE_FLOATS * 4);
            const int ioff = (i + 2) * (5 * HWSZ);
            cp16(stg + tid * 16,         kbase + goff[0] + ioff);
            cp16(stg + (tid + 256) * 16, kbase + goff[1] + ioff);
            if (has3)
                cp16(stg + (tid + 512) * 16, kbase + goff[2] + ioff);
            cp_commit();
        }
    }

    // ---- fused pixel shuffle: out (nd, c, 2H, 2W); row 2h+si, cols 2w..2w+1 ----
    const int h = h0 + tz;
    const int w = w0 + tx;
    float2* o2 = reinterpret_cast<float2*>(out);
    const size_t rowbase = ((size_t)nd * CB) * (2 * HH) + (2 * h + si);
    __stcs(&o2[(rowbase + 0 * 2 * HH) * WW + w], make_float2(a00, a01));
    __stcs(&o2[(rowbase + 1 * 2 * HH) * WW + w], make_float2(a10, a11));
    __stcs(&o2[(rowbase + 2 * 2 * HH) * WW + w], make_float2(a20, a21));
}

extern "C" void kernel_launch(void* const* d_in, const int* in_sizes, int n_in,
                              void* d_out, int out_size)
{
    const float* burst   = (const float*)d_in[0];   // (4,8,3,128,128)
    const float* kernels = (const float*)d_in[1];   // (4,8,4,5,5,128,128)
    float* out = (float*)d_out;                     // (4,8,3,256,256)

    dim3 block(32, 2, 4);                           // 256 threads
    dim3 grid(WW / TW, HH / TH, NB * DB);           // (4, 32, 32) = 4096 blocks
    adaptive_conv_ps_v8<<<grid, block>>>(burst, kernels, out);
}

// round 9
// speedup vs baseline: 1.2108x; 1.0224x over previous
#include <cuda_runtime.h>
#include <cstdint>

// Shapes fixed by the reference
#define NB   4
#define DB   8
#define CB   3
#define RB   4
#define KK   5
#define HH   128
#define WW   128
#define HWSZ (HH * WW)
#define TW   32
#define TH   4
#define SH_  (TH + 4)                 // 8
#define SW_  (TW + 4)                 // 36
#define TILE_FLOATS (CB * SH_ * SW_)  // 864

// i-row chunk: 20 planes (q = r*5+j) x 4 rows x 32 w
#define STAGE_FLOATS (20 * TH * TW)   // 2560
#define NUNITS       (STAGE_FLOATS / 4) // 640 x 16B cp.async units

__device__ __forceinline__ void cp16(uint32_t dst, const float* src) {
    asm volatile("cp.async.cg.shared.global [%0], [%1], 16;"
                 :: "r"(dst), "l"(src) : "memory");
}
__device__ __forceinline__ void cp_commit() {
    asm volatile("cp.async.commit_group;" ::: "memory");
}
template <int N>
__device__ __forceinline__ void cp_wait() {
    asm volatile("cp.async.wait_group %0;" :: "n"(N) : "memory");
}

// Block (32,2,4): tx = pixel col, si = r-group, tz = row. 256 threads, 8 CTAs/SM.
__global__ __launch_bounds__(256, 8)
void adaptive_conv_ps_v8(const float* __restrict__ burst,
                         const float* __restrict__ kernels,
                         float* __restrict__ out)
{
    __shared__ alignas(16) float smem[2 * STAGE_FLOATS + TILE_FLOATS];
    float* sb = smem + 2 * STAGE_FLOATS;          // burst tile [CB][SH_][SW_]
    const uint32_t smem_u32 = (uint32_t)__cvta_generic_to_shared(smem);

    const int nd = blockIdx.z;
    const int h0 = blockIdx.y * TH;
    const int w0 = blockIdx.x * TW;
    const int tx = threadIdx.x;                   // 0..31
    const int si = threadIdx.y;                   // 0..1
    const int tz = threadIdx.z;                   // 0..3
    const int tid = (tz * 2 + si) * 32 + tx;

    const float* kbase = kernels + (size_t)nd * (RB * KK * KK) * HWSZ;

    // ---- per-thread cp.async unit constants (unit u -> plane q, row, 16B seg) ----
    // u = q*32 + row*8 + seg ; plane q = r*5+j ; global plane g = r*25 + i*5 + j
    int goff[3];                                  // element offset, i-term excluded
    #pragma unroll
    for (int k = 0; k < 3; k++) {
        int u = tid + k * 256;
        int q   = u >> 5;
        int row = (u >> 3) & 3;
        int seg = u & 7;
        int r = q / 5, j = q - 5 * r;
        goff[k] = (r * 25 + j) * HWSZ + (h0 + row) * WW + w0 + seg * 4;
    }
    const bool has3 = (tid < NUNITS - 512);       // tid < 128

    // ---- kick off chunks 0 and 1 ----
    #pragma unroll
    for (int c = 0; c < 2; c++) {
        const uint32_t stg = smem_u32 + c * (STAGE_FLOATS * 4);
        cp16(stg + tid * 16,         kbase + goff[0] + c * (5 * HWSZ));
        cp16(stg + (tid + 256) * 16, kbase + goff[1] + c * (5 * HWSZ));
        if (has3)
            cp16(stg + (tid + 512) * 16, kbase + goff[2] + c * (5 * HWSZ));
        cp_commit();
    }

    // ---- stage burst tile (3 ch, halo 2, zero-pad OOB) ----
    const float* bptr = burst + (size_t)nd * CB * HWSZ;
    #pragma unroll
    for (int k = 0; k < 4; k++) {
        int idx = tid + k * 256;
        if (idx < TILE_FLOATS) {
            int c   = idx / (SH_ * SW_);
            int rem = idx - c * (SH_ * SW_);
            int sh  = rem / SW_;
            int sw  = rem - sh * SW_;
            int gh  = h0 + sh - 2;
            int gw  = w0 + sw - 2;
            float v = 0.0f;
            if (gh >= 0 && gh < HH && gw >= 0 && gw < WW)
                v = bptr[c * HWSZ + gh * WW + gw];
            sb[idx] = v;
        }
    }
    __syncthreads();

    float a00 = 0.f, a01 = 0.f;
    float a10 = 0.f, a11 = 0.f;
    float a20 = 0.f, a21 = 0.f;

    #pragma unroll
    for (int i = 0; i < KK; i++) {
        if (i < 4) cp_wait<1>(); else cp_wait<0>();
        __syncthreads();                          // everyone's chunk-i bytes visible

        const float* st = smem + (i & 1) * STAGE_FLOATS;
        #pragma unroll
        for (int j = 0; j < KK; j++) {
            const float k0 = st[(10 * si + j)     * (TH * TW) + tz * TW + tx];
            const float k1 = st[(10 * si + 5 + j) * (TH * TW) + tz * TW + tx];
            const float b0 = sb[(0 * SH_ + tz + i) * SW_ + tx + j];
            const float b1 = sb[(1 * SH_ + tz + i) * SW_ + tx + j];
            const float b2 = sb[(2 * SH_ + tz + i) * SW_ + tx + j];
            a00 = fmaf(k0, b0, a00);  a01 = fmaf(k1, b0, a01);
            a10 = fmaf(k0, b1, a10);  a11 = fmaf(k1, b1, a11);
            a20 = fmaf(k0, b2, a20);  a21 = fmaf(k1, b2, a21);
        }
        __syncthreads();                          // stage free for refill

        if (i + 2 < KK) {                         // refill stage (i&1) with chunk i+2
            const uint32_t stg = smem_u32 + (i & 1) * (STAGE_FLOATS * 4);
            const int ioff = (i + 2) * (5 * HWSZ);
            cp16(stg + tid * 16,         kbase + goff[0] + ioff);
            cp16(stg + (tid + 256) * 16, kbase + goff[1] + ioff);
            if (has3)
                cp16(stg + (tid + 512) * 16, kbase + goff[2] + ioff);
            cp_commit();
        }
    }

    // ---- fused pixel shuffle: out (nd, c, 2H, 2W); row 2h+si, cols 2w..2w+1 ----
    const int h = h0 + tz;
    const int w = w0 + tx;
    float2* o2 = reinterpret_cast<float2*>(out);
    const size_t rowbase = ((size_t)nd * CB) * (2 * HH) + (2 * h + si);
    __stcs(&o2[(rowbase + 0 * 2 * HH) * WW + w], make_float2(a00, a01));
    __stcs(&o2[(rowbase + 1 * 2 * HH) * WW + w], make_float2(a10, a11));
    __stcs(&o2[(rowbase + 2 * 2 * HH) * WW + w], make_float2(a20, a21));
}

extern "C" void kernel_launch(void* const* d_in, const int* in_sizes, int n_in,
                              void* d_out, int out_size)
{
    const float* burst   = (const float*)d_in[0];   // (4,8,3,128,128)
    const float* kernels = (const float*)d_in[1];   // (4,8,4,5,5,128,128)
    float* out = (float*)d_out;                     // (4,8,3,256,256)

    dim3 block(32, 2, 4);                           // 256 threads
    dim3 grid(WW / TW, HH / TH, NB * DB);           // (4, 32, 32) = 4096 blocks
    adaptive_conv_ps_v8<<<grid, block>>>(burst, kernels, out);
}